// round 6
// baseline (speedup 1.0000x reference)
#include <cuda_runtime.h>
#include <math.h>
#include <stdint.h>

#define B_ 8
#define N_ 2048
#define W_ 64
#define R_ 4
#define EPS_ 1e-8f
#define TI_ 128

typedef unsigned long long u64;

// ---------------- device scratch ----------------
__device__ float g_fwd [B_*R_*N_];   // fully corrected forward weights
__device__ float g_bc  [B_*R_*N_];   // bwd correction: pn*S - ell*prn
__device__ float g_bwdp[B_*16*R_*N_];
__device__ float g_cw  [B_*R_*N_];
__device__ float g_gate[B_*R_*3];
__device__ float g_P   [B_*R_];
__device__ float g_S   [B_*R_];

// ---------------- f32x2 helpers ----------------
__device__ __forceinline__ u64 pk(float a, float b){
    u64 r; asm("mov.b64 %0,{%1,%2};" : "=l"(r) : "f"(a), "f"(b)); return r;
}
__device__ __forceinline__ void upk(u64 x, float& a, float& b){
    asm("mov.b64 {%0,%1},%2;" : "=f"(a), "=f"(b) : "l"(x));
}
__device__ __forceinline__ u64 add2(u64 a, u64 b){
    u64 d; asm("add.rn.f32x2 %0,%1,%2;" : "=l"(d) : "l"(a), "l"(b)); return d;
}
__device__ __forceinline__ u64 sub2(u64 a, u64 b){
    u64 d; asm("sub.rn.f32x2 %0,%1,%2;" : "=l"(d) : "l"(a), "l"(b)); return d;
}
__device__ __forceinline__ u64 mul2(u64 a, u64 b){
    u64 d; asm("mul.rn.f32x2 %0,%1,%2;" : "=l"(d) : "l"(a), "l"(b)); return d;
}
__device__ __forceinline__ u64 fma2(u64 a, u64 b, u64 c){
    u64 d; asm("fma.rn.f32x2 %0,%1,%2,%3;" : "=l"(d) : "l"(a), "l"(b), "l"(c)); return d;
}

// ---------------- mbarrier / bulk-copy helpers ----------------
__device__ __forceinline__ uint32_t smem_u32(const void* p){
    return (uint32_t)__cvta_generic_to_shared(p);
}
__device__ __forceinline__ void mbar_init(uint32_t a, uint32_t cnt){
    asm volatile("mbarrier.init.shared.b64 [%0], %1;" :: "r"(a), "r"(cnt) : "memory");
}
__device__ __forceinline__ void mbar_expect(uint32_t a, uint32_t bytes){
    asm volatile("mbarrier.arrive.expect_tx.shared.b64 _, [%0], %1;" :: "r"(a), "r"(bytes) : "memory");
}
__device__ __forceinline__ void bulk_g2s(uint32_t dst, const void* src, uint32_t bytes, uint32_t bar){
    asm volatile("cp.async.bulk.shared::cluster.global.mbarrier::complete_tx::bytes [%0], [%1], %2, [%3];"
                 :: "r"(dst), "l"(src), "r"(bytes), "r"(bar) : "memory");
}
__device__ __forceinline__ void mbar_wait(uint32_t a, uint32_t ph){
    asm volatile("{\n\t.reg .pred P;\n\tWL%=:\n\tmbarrier.try_wait.parity.shared.b64 P, [%0], %1;\n\t@P bra WD%=;\n\tbra WL%=;\n\tWD%=:\n\t}"
                 :: "r"(a), "r"(ph) : "memory");
}

// ================= k_dots: content scores (unscaled), 128 blocks x 512 =================
__global__ void __launch_bounds__(512)
k_dots(const float* __restrict__ mem, const float* __restrict__ controls)
{
    int b = blockIdx.x >> 4, chunk = blockIdx.x & 15;
    int n0 = chunk * 128;
    int tid = threadIdx.x, w = tid >> 5, lane = tid & 31;
    int half = lane >> 4, h = lane & 15;

    __shared__ __align__(16) float s_key[256];
    __shared__ float s_kn[4];

    if (tid < 256) s_key[tid] = controls[b*272 + tid];
    __syncthreads();
    if (w < 4) {
        float x0 = s_key[w*64 + lane], x1 = s_key[w*64 + 32 + lane];
        float q = x0*x0 + x1*x1;
        #pragma unroll
        for (int m = 16; m; m >>= 1) q += __shfl_xor_sync(~0u, q, m);
        if (lane == 0) s_kn[w] = sqrtf(q);
    }
    __syncthreads();

    #pragma unroll
    for (int it = 0; it < 4; ++it) {
        int n = n0 + w*8 + it*2 + half;
        float4 m4 = *(const float4*)(mem + ((size_t)(b*N_ + n))*W_ + h*4);
        float4 k0 = *(const float4*)(s_key + 0*64 + h*4);
        float4 k1 = *(const float4*)(s_key + 1*64 + h*4);
        float4 k2 = *(const float4*)(s_key + 2*64 + h*4);
        float4 k3 = *(const float4*)(s_key + 3*64 + h*4);
        float d0 = m4.x*k0.x + m4.y*k0.y + m4.z*k0.z + m4.w*k0.w;
        float d1 = m4.x*k1.x + m4.y*k1.y + m4.z*k1.z + m4.w*k1.w;
        float d2 = m4.x*k2.x + m4.y*k2.y + m4.z*k2.z + m4.w*k2.w;
        float d3 = m4.x*k3.x + m4.y*k3.y + m4.z*k3.z + m4.w*k3.w;
        float nr = m4.x*m4.x + m4.y*m4.y + m4.z*m4.z + m4.w*m4.w;
        u64 p01 = pk(d0, d1), p23 = pk(d2, d3);
        #pragma unroll
        for (int m = 8; m; m >>= 1) {
            p01 = add2(p01, __shfl_xor_sync(~0u, p01, m));
            p23 = add2(p23, __shfl_xor_sync(~0u, p23, m));
            nr += __shfl_xor_sync(~0u, nr, m);
        }
        if (h == 0) {
            float mns = sqrtf(nr);
            float a0, a1, a2, a3;
            upk(p01, a0, a1); upk(p23, a2, a3);
            g_cw[(b*4+0)*N_ + n] = a0/(s_kn[0]*mns + EPS_);
            g_cw[(b*4+1)*N_ + n] = a1/(s_kn[1]*mns + EPS_);
            g_cw[(b*4+2)*N_ + n] = a2/(s_kn[2]*mns + EPS_);
            g_cw[(b*4+3)*N_ + n] = a3/(s_kn[3]*mns + EPS_);
        }
    }
}

// ================= k_smax: scalars + beta-scaled softmax, one block per (b,r) =================
__global__ void __launch_bounds__(512)
k_smax(const float* __restrict__ controls, const float* __restrict__ ww,
       const float* __restrict__ p, const float* __restrict__ prw,
       float* __restrict__ out)
{
    int br = blockIdx.x, b = br >> 2, r = br & 3;
    int tid = threadIdx.x, warp = tid >> 5, lane = tid & 31;
    __shared__ u64   s_r1[16];
    __shared__ float s_r2[16];
    __shared__ float s_bk[2];

    float accP = 0.f, accS = 0.f;
    for (int k = tid; k < N_; k += 512) {
        float t = prw[br*N_ + k];
        accP += p [b*N_ + k]*t;
        accS += ww[b*N_ + k]*t;
    }
    u64 pp = pk(accP, accS);
    #pragma unroll
    for (int m = 16; m; m >>= 1) pp = add2(pp, __shfl_xor_sync(~0u, pp, m));
    if (lane == 0) s_r1[warp] = pp;
    __syncthreads();
    if (tid == 0) {
        float P = 0.f, S = 0.f;
        #pragma unroll
        for (int i = 0; i < 16; ++i) { float x, y; upk(s_r1[i], x, y); P += x; S += y; }
        g_P[br] = P; g_S[br] = S;
        float x = controls[b*272 + 256 + r];
        s_bk[0] = 1.f + ((x > 15.f) ? x : log1pf(__expf(x)));   // beta
        float e0 = controls[b*272 + 260 + r*3 + 0];
        float e1 = controls[b*272 + 260 + r*3 + 1];
        float e2 = controls[b*272 + 260 + r*3 + 2];
        float mm = fmaxf(e0, fmaxf(e1, e2));
        float x0 = __expf(e0-mm), x1 = __expf(e1-mm), x2 = __expf(e2-mm);
        float inv = 1.f/(x0+x1+x2);
        g_gate[br*3+0] = x0*inv; g_gate[br*3+1] = x1*inv; g_gate[br*3+2] = x2*inv;
    }
    if (tid < 64) out[br*64 + tid] = 0.f;
    __syncthreads();

    float beta = s_bk[0];
    float v[4]; float mx = -1e30f;
    #pragma unroll
    for (int k = 0; k < 4; ++k) { v[k] = g_cw[br*N_ + tid + k*512]*beta; mx = fmaxf(mx, v[k]); }
    #pragma unroll
    for (int m = 16; m; m >>= 1) mx = fmaxf(mx, __shfl_xor_sync(~0u, mx, m));
    if (lane == 0) s_r2[warp] = mx;
    __syncthreads();
    if (tid == 0) { float m2 = s_r2[0]; for (int i = 1; i < 16; ++i) m2 = fmaxf(m2, s_r2[i]); s_bk[1] = m2; }
    __syncthreads();
    mx = s_bk[1];
    float s = 0.f;
    #pragma unroll
    for (int k = 0; k < 4; ++k) { v[k] = __expf(v[k]-mx); s += v[k]; }
    #pragma unroll
    for (int m = 16; m; m >>= 1) s += __shfl_xor_sync(~0u, s, m);
    __syncthreads();
    if (lane == 0) s_r2[warp] = s;
    __syncthreads();
    if (tid == 0) { float t = 0.f; for (int i = 0; i < 16; ++i) t += s_r2[i]; s_bk[0] = 1.f/t; }
    __syncthreads();
    float inv = s_bk[0];
    #pragma unroll
    for (int k = 0; k < 4; ++k) g_cw[br*N_ + tid + k*512] = v[k]*inv;
}

// ================= k_stream: one pass over L, 4-stage x 4-row bulk-async pipeline =================
#define ST_BYTES 32768            // 4 rows x 2048 x 4B
#define NSTG 4
#define SMEM_DYN 166944
#define SP(sel,row,w) s_part[(((sel)*128 + (row))*16) + (w)]

__global__ void __launch_bounds__(512)
k_stream(const float* __restrict__ L, const float* __restrict__ ww,
         const float* __restrict__ prw, const float* __restrict__ p)
{
    extern __shared__ __align__(16) unsigned char dsm[];
    float* stgb   = (float*)(dsm);                 // 4 x 32768
    u64*   s_part = (u64*)  (dsm + 131072);        // [2][128][16]
    float* s_a    = (float*)(dsm + 163840);        // [128]
    float* s_pi   = (float*)(dsm + 164352);        // [4][128]
    float* s_diag = (float*)(dsm + 166400);        // [128]
    u64*   s_bar  = (u64*)  (dsm + 166912);        // [4]

    int b = blockIdx.x >> 4, tile = blockIdx.x & 15, i0 = tile*TI_;
    int tid = threadIdx.x, w = tid >> 5, lane = tid & 31;
    int half = lane >> 4, h = lane & 15;

    if (tid < TI_) s_a[tid] = 1.f - ww[b*N_ + i0 + tid];
    if (tid < R_*TI_) s_pi[tid] = prw[(b*4 + (tid >> 7))*N_ + i0 + (tid & 127)];

    uint32_t bar0 = smem_u32(s_bar);
    uint32_t st0  = smem_u32(stgb);
    if (tid == 0) {
        #pragma unroll
        for (int s = 0; s < NSTG; ++s) mbar_init(bar0 + s*8, 1);
    }
    __syncthreads();

    const char* src = (const char*)(L + ((size_t)(b*N_ + i0))*N_);
    if (tid == 0) {
        #pragma unroll
        for (int s = 0; s < NSTG; ++s) {
            mbar_expect(bar0 + s*8, ST_BYTES);
            bulk_g2s(st0 + s*ST_BYTES, src + (size_t)s*ST_BYTES, ST_BYTES, bar0 + s*8);
        }
    }

    int jA = w*128 + h*4, jB = jA + 64;
    u64 pj[4][4];
    #pragma unroll
    for (int r = 0; r < 4; ++r) {
        float4 A  = *(const float4*)(prw + (b*4+r)*N_ + jA);
        float4 Bv = *(const float4*)(prw + (b*4+r)*N_ + jB);
        pj[r][0] = pk(A.x, A.y);  pj[r][1] = pk(A.z, A.w);
        pj[r][2] = pk(Bv.x, Bv.y); pj[r][3] = pk(Bv.z, Bv.w);
    }
    float4 wA = *(const float4*)(ww + b*N_ + jA);
    float4 wB = *(const float4*)(ww + b*N_ + jB);
    u64 wj[4] = { pk(wA.x,wA.y), pk(wA.z,wA.w), pk(wB.x,wB.y), pk(wB.z,wB.w) };

    u64 bw[4][4];
    #pragma unroll
    for (int r = 0; r < 4; ++r)
        #pragma unroll
        for (int k = 0; k < 4; ++k) bw[r][k] = 0ull;

    for (int g = 0; g < 32; ++g) {
        int s = g & 3;
        uint32_t ph = (g >> 2) & 1;
        mbar_wait(bar0 + s*8, ph);
        const float* stg = stgb + s*8192;

        // diag elements for these 4 rows live in this stage
        if (tid < 4) s_diag[g*4 + tid] = stg[tid*2048 + i0 + g*4 + tid];

        #pragma unroll
        for (int it = 0; it < 2; ++it) {
            int lrow = it*2 + half;
            int row  = g*4 + lrow;
            float4 A  = *(const float4*)(stg + lrow*2048 + jA);
            float4 Bv = *(const float4*)(stg + lrow*2048 + jB);
            u64 l0 = pk(A.x,A.y), l1 = pk(A.z,A.w), l2 = pk(Bv.x,Bv.y), l3 = pk(Bv.z,Bv.w);
            float a = s_a[row];
            u64 av = pk(a, a);
            u64 c0 = mul2(sub2(av, wj[0]), l0);
            u64 c1 = mul2(sub2(av, wj[1]), l1);
            u64 c2 = mul2(sub2(av, wj[2]), l2);
            u64 c3 = mul2(sub2(av, wj[3]), l3);

            float f[4];
            #pragma unroll
            for (int r = 0; r < 4; ++r) {
                u64 t = mul2(c0, pj[r][0]);
                t = fma2(c1, pj[r][1], t);
                t = fma2(c2, pj[r][2], t);
                t = fma2(c3, pj[r][3], t);
                float x, y; upk(t, x, y); f[r] = x + y;
                float pi = s_pi[r*128 + row];
                u64 pr = pk(pi, pi);
                bw[r][0] = fma2(c0, pr, bw[r][0]);
                bw[r][1] = fma2(c1, pr, bw[r][1]);
                bw[r][2] = fma2(c2, pr, bw[r][2]);
                bw[r][3] = fma2(c3, pr, bw[r][3]);
            }
            u64 f01 = pk(f[0], f[1]), f23 = pk(f[2], f[3]);
            #pragma unroll
            for (int m = 8; m; m >>= 1) {
                f01 = add2(f01, __shfl_xor_sync(~0u, f01, m));
                f23 = add2(f23, __shfl_xor_sync(~0u, f23, m));
            }
            if (h == 0) { SP(0, row, w) = f01; SP(1, row, w) = f23; }
        }
        __syncthreads();
        if (tid == 0 && g + NSTG < 32) {
            mbar_expect(bar0 + s*8, ST_BYTES);
            bulk_g2s(st0 + s*ST_BYTES, src + (size_t)(g + NSTG)*ST_BYTES, ST_BYTES, bar0 + s*8);
        }
    }

    // bwd: combine halves, flush per-tile partial (vector stores)
    #pragma unroll
    for (int r = 0; r < 4; ++r)
        #pragma unroll
        for (int k = 0; k < 4; ++k)
            bw[r][k] = add2(bw[r][k], __shfl_xor_sync(~0u, bw[r][k], 16));
    if (half == 0) {
        #pragma unroll
        for (int r = 0; r < 4; ++r) {
            float* dst = g_bwdp + ((size_t)((b*16 + tile)*4 + r))*N_;
            ulonglong2 v0; v0.x = bw[r][0]; v0.y = bw[r][1];
            ulonglong2 v1; v1.x = bw[r][2]; v1.y = bw[r][3];
            *(ulonglong2*)(dst + jA) = v0;
            *(ulonglong2*)(dst + jB) = v1;
        }
    }

    // fwd fold + rank-1 + diag corrections; also emit bwd correction g_bc
    {
        int row = tid >> 2, r = tid & 3;
        int br = b*4 + r;
        int n = i0 + row;
        const float* sp = (const float*)&SP(r >> 1, row, 0);
        float sfold = 0.f;
        #pragma unroll
        for (int w2 = 0; w2 < 16; ++w2) sfold += sp[w2*2 + (r & 1)];
        float wn  = 1.f - s_a[row];
        float pn  = p[b*N_ + n];
        float prn = s_pi[r*128 + row];
        float ell = (1.f - 2.f*wn)*s_diag[row] + wn*pn;
        g_fwd[br*N_ + n] = sfold + wn*g_P[br] - ell*prn;
        g_bc [br*N_ + n] = pn*g_S[br] - ell*prn;
    }
}

// ================= k_post: rw assembly + read vector, 128 blocks x 256 =================
__global__ void __launch_bounds__(256)
k_post(const float* __restrict__ mem, float* __restrict__ out)
{
    int b = blockIdx.x >> 4, c = blockIdx.x & 15;
    int n0 = c*128;
    int tid = threadIdx.x, warp = tid >> 5, lane = tid & 31;
    __shared__ float s_rw[4][128];
    __shared__ float s_g[12];
    __shared__ float s_acc[8][4][64];

    if (tid < 12) s_g[tid] = g_gate[b*12 + tid];
    __syncthreads();

    #pragma unroll
    for (int kk = 0; kk < 2; ++kk) {
        int item = tid + kk*256;
        int r = item >> 7, nl = item & 127;
        int br = b*4 + r, n = n0 + nl;
        float bp = 0.f;
        #pragma unroll
        for (int t = 0; t < 16; ++t)
            bp += g_bwdp[((size_t)((b*16 + t)*4 + r))*N_ + n];
        s_rw[r][nl] = s_g[r*3+0]*g_fwd[br*N_ + n]
                    + s_g[r*3+1]*(bp + g_bc[br*N_ + n])
                    + s_g[r*3+2]*g_cw[br*N_ + n];
    }
    __syncthreads();

    float2 acc[4];
    #pragma unroll
    for (int r = 0; r < 4; ++r) { acc[r].x = 0.f; acc[r].y = 0.f; }
    #pragma unroll 4
    for (int k = 0; k < 16; ++k) {
        int nl = warp*16 + k;
        float2 m = *(const float2*)(mem + ((size_t)(b*N_ + n0 + nl))*W_ + lane*2);
        #pragma unroll
        for (int r = 0; r < 4; ++r) {
            float rv = s_rw[r][nl];
            acc[r].x += m.x*rv;
            acc[r].y += m.y*rv;
        }
    }
    #pragma unroll
    for (int r = 0; r < 4; ++r) {
        s_acc[warp][r][lane*2]   = acc[r].x;
        s_acc[warp][r][lane*2+1] = acc[r].y;
    }
    __syncthreads();
    {
        int r = tid >> 6, wd = tid & 63;
        float s = 0.f;
        #pragma unroll
        for (int k = 0; k < 8; ++k) s += s_acc[k][r][wd];
        atomicAdd(&out[(b*4 + r)*64 + wd], s);
    }
}

// ================= launcher =================
extern "C" void kernel_launch(void* const* d_in, const int* in_sizes, int n_in,
                              void* d_out, int out_size)
{
    const float* mem      = (const float*)d_in[0];
    const float* controls = (const float*)d_in[1];
    const float* ww       = (const float*)d_in[2];
    const float* L        = (const float*)d_in[3];
    const float* p        = (const float*)d_in[4];
    const float* prw      = (const float*)d_in[5];
    float* out = (float*)d_out;

    cudaFuncSetAttribute(k_stream, cudaFuncAttributeMaxDynamicSharedMemorySize, SMEM_DYN);

    k_dots  <<<B_*16, 512>>>(mem, controls);
    k_smax  <<<B_*R_, 512>>>(controls, ww, p, prw, out);
    k_stream<<<B_*16, 512, SMEM_DYN>>>(L, ww, prw, p);
    k_post  <<<B_*16, 256>>>(mem, out);
}

// round 7
// speedup vs baseline: 1.0334x; 1.0334x over previous
#include <cuda_runtime.h>
#include <math.h>
#include <stdint.h>

#define B_ 8
#define N_ 2048
#define W_ 64
#define R_ 4
#define EPS_ 1e-8f
#define TI_ 128

typedef unsigned long long u64;

// ---------------- device scratch ----------------
__device__ float g_fwd [B_*R_*N_];   // fully corrected forward weights
__device__ float g_bwd [B_*R_*N_];   // atomically accumulated bwd core sums
__device__ float g_bc  [B_*R_*N_];   // bwd correction: pn*S - ell*prn
__device__ float g_cw  [B_*R_*N_];
__device__ float g_gate[B_*R_*3];
__device__ float g_P   [B_*R_];
__device__ float g_S   [B_*R_];

// ---------------- f32x2 helpers ----------------
__device__ __forceinline__ u64 pk(float a, float b){
    u64 r; asm("mov.b64 %0,{%1,%2};" : "=l"(r) : "f"(a), "f"(b)); return r;
}
__device__ __forceinline__ void upk(u64 x, float& a, float& b){
    asm("mov.b64 {%0,%1},%2;" : "=f"(a), "=f"(b) : "l"(x));
}
__device__ __forceinline__ u64 add2(u64 a, u64 b){
    u64 d; asm("add.rn.f32x2 %0,%1,%2;" : "=l"(d) : "l"(a), "l"(b)); return d;
}
__device__ __forceinline__ u64 sub2(u64 a, u64 b){
    u64 d; asm("sub.rn.f32x2 %0,%1,%2;" : "=l"(d) : "l"(a), "l"(b)); return d;
}
__device__ __forceinline__ u64 mul2(u64 a, u64 b){
    u64 d; asm("mul.rn.f32x2 %0,%1,%2;" : "=l"(d) : "l"(a), "l"(b)); return d;
}
__device__ __forceinline__ u64 fma2(u64 a, u64 b, u64 c){
    u64 d; asm("fma.rn.f32x2 %0,%1,%2,%3;" : "=l"(d) : "l"(a), "l"(b), "l"(c)); return d;
}

// ---------------- mbarrier / bulk-copy helpers ----------------
__device__ __forceinline__ uint32_t smem_u32(const void* p){
    return (uint32_t)__cvta_generic_to_shared(p);
}
__device__ __forceinline__ void mbar_init(uint32_t a, uint32_t cnt){
    asm volatile("mbarrier.init.shared.b64 [%0], %1;" :: "r"(a), "r"(cnt) : "memory");
}
__device__ __forceinline__ void mbar_expect(uint32_t a, uint32_t bytes){
    asm volatile("mbarrier.arrive.expect_tx.shared.b64 _, [%0], %1;" :: "r"(a), "r"(bytes) : "memory");
}
__device__ __forceinline__ void bulk_g2s(uint32_t dst, const void* src, uint32_t bytes, uint32_t bar){
    asm volatile("cp.async.bulk.shared::cluster.global.mbarrier::complete_tx::bytes [%0], [%1], %2, [%3];"
                 :: "r"(dst), "l"(src), "r"(bytes), "r"(bar) : "memory");
}
__device__ __forceinline__ void mbar_wait(uint32_t a, uint32_t ph){
    asm volatile("{\n\t.reg .pred P;\n\tWL%=:\n\tmbarrier.try_wait.parity.shared.b64 P, [%0], %1;\n\t@P bra WD%=;\n\tbra WL%=;\n\tWD%=:\n\t}"
                 :: "r"(a), "r"(ph) : "memory");
}

// ================= k_dots: content scores (unscaled), 128 blocks x 512 =================
__global__ void __launch_bounds__(512)
k_dots(const float* __restrict__ mem, const float* __restrict__ controls)
{
    int b = blockIdx.x >> 4, chunk = blockIdx.x & 15;
    int n0 = chunk * 128;
    int tid = threadIdx.x, w = tid >> 5, lane = tid & 31;
    int half = lane >> 4, h = lane & 15;

    __shared__ __align__(16) float s_key[256];
    __shared__ float s_kn[4];

    if (tid < 256) s_key[tid] = controls[b*272 + tid];
    __syncthreads();
    if (w < 4) {
        float x0 = s_key[w*64 + lane], x1 = s_key[w*64 + 32 + lane];
        float q = x0*x0 + x1*x1;
        #pragma unroll
        for (int m = 16; m; m >>= 1) q += __shfl_xor_sync(~0u, q, m);
        if (lane == 0) s_kn[w] = sqrtf(q);
    }
    __syncthreads();

    #pragma unroll
    for (int it = 0; it < 4; ++it) {
        int n = n0 + w*8 + it*2 + half;
        float4 m4 = *(const float4*)(mem + ((size_t)(b*N_ + n))*W_ + h*4);
        float4 k0 = *(const float4*)(s_key + 0*64 + h*4);
        float4 k1 = *(const float4*)(s_key + 1*64 + h*4);
        float4 k2 = *(const float4*)(s_key + 2*64 + h*4);
        float4 k3 = *(const float4*)(s_key + 3*64 + h*4);
        float d0 = m4.x*k0.x + m4.y*k0.y + m4.z*k0.z + m4.w*k0.w;
        float d1 = m4.x*k1.x + m4.y*k1.y + m4.z*k1.z + m4.w*k1.w;
        float d2 = m4.x*k2.x + m4.y*k2.y + m4.z*k2.z + m4.w*k2.w;
        float d3 = m4.x*k3.x + m4.y*k3.y + m4.z*k3.z + m4.w*k3.w;
        float nr = m4.x*m4.x + m4.y*m4.y + m4.z*m4.z + m4.w*m4.w;
        u64 p01 = pk(d0, d1), p23 = pk(d2, d3);
        #pragma unroll
        for (int m = 8; m; m >>= 1) {
            p01 = add2(p01, __shfl_xor_sync(~0u, p01, m));
            p23 = add2(p23, __shfl_xor_sync(~0u, p23, m));
            nr += __shfl_xor_sync(~0u, nr, m);
        }
        if (h == 0) {
            float mns = sqrtf(nr);
            float a0, a1, a2, a3;
            upk(p01, a0, a1); upk(p23, a2, a3);
            g_cw[(b*4+0)*N_ + n] = a0/(s_kn[0]*mns + EPS_);
            g_cw[(b*4+1)*N_ + n] = a1/(s_kn[1]*mns + EPS_);
            g_cw[(b*4+2)*N_ + n] = a2/(s_kn[2]*mns + EPS_);
            g_cw[(b*4+3)*N_ + n] = a3/(s_kn[3]*mns + EPS_);
        }
    }
}

// ================= k_smax: scalars + softmax + zero g_bwd, one block per (b,r) =================
__global__ void __launch_bounds__(512)
k_smax(const float* __restrict__ controls, const float* __restrict__ ww,
       const float* __restrict__ p, const float* __restrict__ prw,
       float* __restrict__ out)
{
    int br = blockIdx.x, b = br >> 2, r = br & 3;
    int tid = threadIdx.x, warp = tid >> 5, lane = tid & 31;
    __shared__ u64   s_r1[16];
    __shared__ float s_r2[16];
    __shared__ float s_bk[2];

    // zero this (b,r)'s slice of g_bwd (needed before k_stream's REDG flush)
    for (int k = tid; k < N_; k += 512) g_bwd[br*N_ + k] = 0.f;

    float accP = 0.f, accS = 0.f;
    for (int k = tid; k < N_; k += 512) {
        float t = prw[br*N_ + k];
        accP += p [b*N_ + k]*t;
        accS += ww[b*N_ + k]*t;
    }
    u64 pp = pk(accP, accS);
    #pragma unroll
    for (int m = 16; m; m >>= 1) pp = add2(pp, __shfl_xor_sync(~0u, pp, m));
    if (lane == 0) s_r1[warp] = pp;
    __syncthreads();
    if (tid == 0) {
        float P = 0.f, S = 0.f;
        #pragma unroll
        for (int i = 0; i < 16; ++i) { float x, y; upk(s_r1[i], x, y); P += x; S += y; }
        g_P[br] = P; g_S[br] = S;
        float x = controls[b*272 + 256 + r];
        s_bk[0] = 1.f + ((x > 15.f) ? x : log1pf(__expf(x)));   // beta
        float e0 = controls[b*272 + 260 + r*3 + 0];
        float e1 = controls[b*272 + 260 + r*3 + 1];
        float e2 = controls[b*272 + 260 + r*3 + 2];
        float mm = fmaxf(e0, fmaxf(e1, e2));
        float x0 = __expf(e0-mm), x1 = __expf(e1-mm), x2 = __expf(e2-mm);
        float inv = 1.f/(x0+x1+x2);
        g_gate[br*3+0] = x0*inv; g_gate[br*3+1] = x1*inv; g_gate[br*3+2] = x2*inv;
    }
    if (tid < 64) out[br*64 + tid] = 0.f;
    __syncthreads();

    float beta = s_bk[0];
    float v[4]; float mx = -1e30f;
    #pragma unroll
    for (int k = 0; k < 4; ++k) { v[k] = g_cw[br*N_ + tid + k*512]*beta; mx = fmaxf(mx, v[k]); }
    #pragma unroll
    for (int m = 16; m; m >>= 1) mx = fmaxf(mx, __shfl_xor_sync(~0u, mx, m));
    if (lane == 0) s_r2[warp] = mx;
    __syncthreads();
    if (tid == 0) { float m2 = s_r2[0]; for (int i = 1; i < 16; ++i) m2 = fmaxf(m2, s_r2[i]); s_bk[1] = m2; }
    __syncthreads();
    mx = s_bk[1];
    float s = 0.f;
    #pragma unroll
    for (int k = 0; k < 4; ++k) { v[k] = __expf(v[k]-mx); s += v[k]; }
    #pragma unroll
    for (int m = 16; m; m >>= 1) s += __shfl_xor_sync(~0u, s, m);
    __syncthreads();
    if (lane == 0) s_r2[warp] = s;
    __syncthreads();
    if (tid == 0) { float t = 0.f; for (int i = 0; i < 16; ++i) t += s_r2[i]; s_bk[0] = 1.f/t; }
    __syncthreads();
    float inv = s_bk[0];
    #pragma unroll
    for (int k = 0; k < 4; ++k) g_cw[br*N_ + tid + k*512] = v[k]*inv;
}

// ================= k_stream: one pass over L, 2-stage x 8-row bulk-async pipeline =================
#define ST_BYTES 65536            // 8 rows x 2048 x 4B
#define SMEM_DYN 166928
#define SP(sel,row,w) s_part[(((sel)*128 + (row))*16) + (w)]

__global__ void __launch_bounds__(512)
k_stream(const float* __restrict__ L, const float* __restrict__ ww,
         const float* __restrict__ prw, const float* __restrict__ p)
{
    extern __shared__ __align__(16) unsigned char dsm[];
    float* stgb   = (float*)(dsm);                 // 2 x 65536
    u64*   s_part = (u64*)  (dsm + 131072);        // [2][128][16]
    float* s_a    = (float*)(dsm + 163840);        // [128]
    float* s_pi   = (float*)(dsm + 164352);        // [4][128]
    float* s_diag = (float*)(dsm + 166400);        // [128]
    u64*   s_bar  = (u64*)  (dsm + 166912);        // [2]

    int b = blockIdx.x >> 4, tile = blockIdx.x & 15, i0 = tile*TI_;
    int tid = threadIdx.x, w = tid >> 5, lane = tid & 31;
    int half = lane >> 4, h = lane & 15;

    if (tid < TI_) s_a[tid] = 1.f - ww[b*N_ + i0 + tid];
    if (tid < R_*TI_) s_pi[tid] = prw[(b*4 + (tid >> 7))*N_ + i0 + (tid & 127)];

    uint32_t bar0 = smem_u32(s_bar);
    uint32_t st0  = smem_u32(stgb);
    if (tid == 0) { mbar_init(bar0, 1); mbar_init(bar0 + 8, 1); }
    __syncthreads();

    const char* src = (const char*)(L + ((size_t)(b*N_ + i0))*N_);
    if (tid == 0) {
        mbar_expect(bar0,     ST_BYTES); bulk_g2s(st0,            src,            ST_BYTES, bar0);
        mbar_expect(bar0 + 8, ST_BYTES); bulk_g2s(st0 + ST_BYTES, src + ST_BYTES, ST_BYTES, bar0 + 8);
    }

    int jA = w*128 + h*4, jB = jA + 64;
    u64 pj[4][4];
    #pragma unroll
    for (int r = 0; r < 4; ++r) {
        float4 A  = *(const float4*)(prw + (b*4+r)*N_ + jA);
        float4 Bv = *(const float4*)(prw + (b*4+r)*N_ + jB);
        pj[r][0] = pk(A.x, A.y);  pj[r][1] = pk(A.z, A.w);
        pj[r][2] = pk(Bv.x, Bv.y); pj[r][3] = pk(Bv.z, Bv.w);
    }
    float4 wA = *(const float4*)(ww + b*N_ + jA);
    float4 wB = *(const float4*)(ww + b*N_ + jB);
    u64 wj[4] = { pk(wA.x,wA.y), pk(wA.z,wA.w), pk(wB.x,wB.y), pk(wB.z,wB.w) };

    u64 bw[4][4];
    #pragma unroll
    for (int r = 0; r < 4; ++r)
        #pragma unroll
        for (int k = 0; k < 4; ++k) bw[r][k] = 0ull;

    for (int g = 0; g < 16; ++g) {
        int s = g & 1;
        uint32_t ph = (g >> 1) & 1;
        mbar_wait(bar0 + s*8, ph);
        const float* stg = stgb + s*16384;

        // diag elements for these 8 rows live in this stage
        if (tid < 8) s_diag[g*8 + tid] = stg[tid*2048 + i0 + g*8 + tid];

        #pragma unroll
        for (int it = 0; it < 4; ++it) {
            int lrow = it*2 + half;
            int row  = g*8 + lrow;
            float4 A  = *(const float4*)(stg + lrow*2048 + jA);
            float4 Bv = *(const float4*)(stg + lrow*2048 + jB);
            u64 l0 = pk(A.x,A.y), l1 = pk(A.z,A.w), l2 = pk(Bv.x,Bv.y), l3 = pk(Bv.z,Bv.w);
            float a = s_a[row];
            u64 av = pk(a, a);
            u64 c0 = mul2(sub2(av, wj[0]), l0);
            u64 c1 = mul2(sub2(av, wj[1]), l1);
            u64 c2 = mul2(sub2(av, wj[2]), l2);
            u64 c3 = mul2(sub2(av, wj[3]), l3);

            float f[4];
            #pragma unroll
            for (int r = 0; r < 4; ++r) {
                u64 t = mul2(c0, pj[r][0]);
                t = fma2(c1, pj[r][1], t);
                t = fma2(c2, pj[r][2], t);
                t = fma2(c3, pj[r][3], t);
                float x, y; upk(t, x, y); f[r] = x + y;
                float pi = s_pi[r*128 + row];
                u64 pr = pk(pi, pi);
                bw[r][0] = fma2(c0, pr, bw[r][0]);
                bw[r][1] = fma2(c1, pr, bw[r][1]);
                bw[r][2] = fma2(c2, pr, bw[r][2]);
                bw[r][3] = fma2(c3, pr, bw[r][3]);
            }
            u64 f01 = pk(f[0], f[1]), f23 = pk(f[2], f[3]);
            #pragma unroll
            for (int m = 8; m; m >>= 1) {
                f01 = add2(f01, __shfl_xor_sync(~0u, f01, m));
                f23 = add2(f23, __shfl_xor_sync(~0u, f23, m));
            }
            if (h == 0) { SP(0, row, w) = f01; SP(1, row, w) = f23; }
        }
        __syncthreads();
        if (tid == 0 && g + 2 < 16) {
            mbar_expect(bar0 + s*8, ST_BYTES);
            bulk_g2s(st0 + s*ST_BYTES, src + (size_t)(g + 2)*ST_BYTES, ST_BYTES, bar0 + s*8);
        }
    }

    // bwd: combine halves, REDG-accumulate into g_bwd (no partial buffers)
    #pragma unroll
    for (int r = 0; r < 4; ++r)
        #pragma unroll
        for (int k = 0; k < 4; ++k)
            bw[r][k] = add2(bw[r][k], __shfl_xor_sync(~0u, bw[r][k], 16));
    if (half == 0) {
        #pragma unroll
        for (int r = 0; r < 4; ++r) {
            float* dst = g_bwd + (size_t)(b*4 + r)*N_;
            float x0, x1, x2, x3, x4, x5, x6, x7;
            upk(bw[r][0], x0, x1); upk(bw[r][1], x2, x3);
            upk(bw[r][2], x4, x5); upk(bw[r][3], x6, x7);
            atomicAdd(dst + jA + 0, x0); atomicAdd(dst + jA + 1, x1);
            atomicAdd(dst + jA + 2, x2); atomicAdd(dst + jA + 3, x3);
            atomicAdd(dst + jB + 0, x4); atomicAdd(dst + jB + 1, x5);
            atomicAdd(dst + jB + 2, x6); atomicAdd(dst + jB + 3, x7);
        }
    }

    // fwd fold + rank-1 + diag corrections; emit bwd correction g_bc
    {
        int row = tid >> 2, r = tid & 3;
        int br = b*4 + r;
        int n = i0 + row;
        const float* sp = (const float*)&SP(r >> 1, row, 0);
        float sfold = 0.f;
        #pragma unroll
        for (int w2 = 0; w2 < 16; ++w2) sfold += sp[w2*2 + (r & 1)];
        float wn  = 1.f - s_a[row];
        float pn  = p[b*N_ + n];
        float prn = s_pi[r*128 + row];
        float ell = (1.f - 2.f*wn)*s_diag[row] + wn*pn;
        g_fwd[br*N_ + n] = sfold + wn*g_P[br] - ell*prn;
        g_bc [br*N_ + n] = pn*g_S[br] - ell*prn;
    }
}

// ================= k_post: rw assembly + read vector, 128 blocks x 256 =================
__global__ void __launch_bounds__(256)
k_post(const float* __restrict__ mem, float* __restrict__ out)
{
    int b = blockIdx.x >> 4, c = blockIdx.x & 15;
    int n0 = c*128;
    int tid = threadIdx.x, warp = tid >> 5, lane = tid & 31;
    __shared__ float s_rw[4][128];
    __shared__ float s_g[12];
    __shared__ float s_acc[8][4][64];

    if (tid < 12) s_g[tid] = g_gate[b*12 + tid];
    __syncthreads();

    #pragma unroll
    for (int kk = 0; kk < 2; ++kk) {
        int item = tid + kk*256;
        int r = item >> 7, nl = item & 127;
        int br = b*4 + r, n = n0 + nl;
        s_rw[r][nl] = s_g[r*3+0]*g_fwd[br*N_ + n]
                    + s_g[r*3+1]*(g_bwd[br*N_ + n] + g_bc[br*N_ + n])
                    + s_g[r*3+2]*g_cw[br*N_ + n];
    }
    __syncthreads();

    float2 acc[4];
    #pragma unroll
    for (int r = 0; r < 4; ++r) { acc[r].x = 0.f; acc[r].y = 0.f; }
    #pragma unroll 8
    for (int k = 0; k < 16; ++k) {
        int nl = warp*16 + k;
        float2 m = *(const float2*)(mem + ((size_t)(b*N_ + n0 + nl))*W_ + lane*2);
        #pragma unroll
        for (int r = 0; r < 4; ++r) {
            float rv = s_rw[r][nl];
            acc[r].x += m.x*rv;
            acc[r].y += m.y*rv;
        }
    }
    #pragma unroll
    for (int r = 0; r < 4; ++r) {
        s_acc[warp][r][lane*2]   = acc[r].x;
        s_acc[warp][r][lane*2+1] = acc[r].y;
    }
    __syncthreads();
    {
        int r = tid >> 6, wd = tid & 63;
        float s = 0.f;
        #pragma unroll
        for (int k = 0; k < 8; ++k) s += s_acc[k][r][wd];
        atomicAdd(&out[(b*4 + r)*64 + wd], s);
    }
}

// ================= launcher =================
extern "C" void kernel_launch(void* const* d_in, const int* in_sizes, int n_in,
                              void* d_out, int out_size)
{
    const float* mem      = (const float*)d_in[0];
    const float* controls = (const float*)d_in[1];
    const float* ww       = (const float*)d_in[2];
    const float* L        = (const float*)d_in[3];
    const float* p        = (const float*)d_in[4];
    const float* prw      = (const float*)d_in[5];
    float* out = (float*)d_out;

    cudaFuncSetAttribute(k_stream, cudaFuncAttributeMaxDynamicSharedMemorySize, SMEM_DYN);

    k_dots  <<<B_*16, 512>>>(mem, controls);
    k_smax  <<<B_*R_, 512>>>(controls, ww, p, prw, out);
    k_stream<<<B_*16, 512, SMEM_DYN>>>(L, ww, prw, p);
    k_post  <<<B_*16, 256>>>(mem, out);
}

// round 8
// speedup vs baseline: 1.2184x; 1.1791x over previous
#include <cuda_runtime.h>
#include <math.h>
#include <stdint.h>

#define B_ 8
#define N_ 2048
#define W_ 64
#define R_ 4
#define EPS_ 1e-8f
#define TI_ 128

typedef unsigned long long u64;

// ---------------- device scratch ----------------
__device__ float g_fwd [B_*R_*N_];   // fully corrected forward weights
__device__ float g_bwd [B_*R_*N_];   // atomically accumulated bwd core sums
__device__ float g_bc  [B_*R_*N_];   // bwd correction: pn*S - ell*prn
__device__ float g_cw  [B_*R_*N_];
__device__ float g_gate[B_*R_*3];
__device__ float g_P   [B_*R_];
__device__ float g_S   [B_*R_];

// ---------------- f32x2 helpers ----------------
__device__ __forceinline__ u64 pk(float a, float b){
    u64 r; asm("mov.b64 %0,{%1,%2};" : "=l"(r) : "f"(a), "f"(b)); return r;
}
__device__ __forceinline__ void upk(u64 x, float& a, float& b){
    asm("mov.b64 {%0,%1},%2;" : "=f"(a), "=f"(b) : "l"(x));
}
__device__ __forceinline__ u64 add2(u64 a, u64 b){
    u64 d; asm("add.rn.f32x2 %0,%1,%2;" : "=l"(d) : "l"(a), "l"(b)); return d;
}
__device__ __forceinline__ u64 sub2(u64 a, u64 b){
    u64 d; asm("sub.rn.f32x2 %0,%1,%2;" : "=l"(d) : "l"(a), "l"(b)); return d;
}
__device__ __forceinline__ u64 mul2(u64 a, u64 b){
    u64 d; asm("mul.rn.f32x2 %0,%1,%2;" : "=l"(d) : "l"(a), "l"(b)); return d;
}
__device__ __forceinline__ u64 fma2(u64 a, u64 b, u64 c){
    u64 d; asm("fma.rn.f32x2 %0,%1,%2,%3;" : "=l"(d) : "l"(a), "l"(b), "l"(c)); return d;
}

// ================= k_dots: content scores (unscaled), 128 blocks x 512 =================
__global__ void __launch_bounds__(512)
k_dots(const float* __restrict__ mem, const float* __restrict__ controls)
{
    int b = blockIdx.x >> 4, chunk = blockIdx.x & 15;
    int n0 = chunk * 128;
    int tid = threadIdx.x, w = tid >> 5, lane = tid & 31;
    int half = lane >> 4, h = lane & 15;

    __shared__ __align__(16) float s_key[256];
    __shared__ float s_kn[4];

    if (tid < 256) s_key[tid] = controls[b*272 + tid];
    __syncthreads();
    if (w < 4) {
        float x0 = s_key[w*64 + lane], x1 = s_key[w*64 + 32 + lane];
        float q = x0*x0 + x1*x1;
        #pragma unroll
        for (int m = 16; m; m >>= 1) q += __shfl_xor_sync(~0u, q, m);
        if (lane == 0) s_kn[w] = sqrtf(q);
    }
    __syncthreads();

    #pragma unroll
    for (int it = 0; it < 4; ++it) {
        int n = n0 + w*8 + it*2 + half;
        float4 m4 = *(const float4*)(mem + ((size_t)(b*N_ + n))*W_ + h*4);
        float4 k0 = *(const float4*)(s_key + 0*64 + h*4);
        float4 k1 = *(const float4*)(s_key + 1*64 + h*4);
        float4 k2 = *(const float4*)(s_key + 2*64 + h*4);
        float4 k3 = *(const float4*)(s_key + 3*64 + h*4);
        float d0 = m4.x*k0.x + m4.y*k0.y + m4.z*k0.z + m4.w*k0.w;
        float d1 = m4.x*k1.x + m4.y*k1.y + m4.z*k1.z + m4.w*k1.w;
        float d2 = m4.x*k2.x + m4.y*k2.y + m4.z*k2.z + m4.w*k2.w;
        float d3 = m4.x*k3.x + m4.y*k3.y + m4.z*k3.z + m4.w*k3.w;
        float nr = m4.x*m4.x + m4.y*m4.y + m4.z*m4.z + m4.w*m4.w;
        u64 p01 = pk(d0, d1), p23 = pk(d2, d3);
        #pragma unroll
        for (int m = 8; m; m >>= 1) {
            p01 = add2(p01, __shfl_xor_sync(~0u, p01, m));
            p23 = add2(p23, __shfl_xor_sync(~0u, p23, m));
            nr += __shfl_xor_sync(~0u, nr, m);
        }
        if (h == 0) {
            float mns = sqrtf(nr);
            float a0, a1, a2, a3;
            upk(p01, a0, a1); upk(p23, a2, a3);
            g_cw[(b*4+0)*N_ + n] = a0/(s_kn[0]*mns + EPS_);
            g_cw[(b*4+1)*N_ + n] = a1/(s_kn[1]*mns + EPS_);
            g_cw[(b*4+2)*N_ + n] = a2/(s_kn[2]*mns + EPS_);
            g_cw[(b*4+3)*N_ + n] = a3/(s_kn[3]*mns + EPS_);
        }
    }
}

// ================= k_smax: scalars + softmax + zero g_bwd, one block per (b,r) =================
__global__ void __launch_bounds__(512)
k_smax(const float* __restrict__ controls, const float* __restrict__ ww,
       const float* __restrict__ p, const float* __restrict__ prw,
       float* __restrict__ out)
{
    int br = blockIdx.x, b = br >> 2, r = br & 3;
    int tid = threadIdx.x, warp = tid >> 5, lane = tid & 31;
    __shared__ u64   s_r1[16];
    __shared__ float s_r2[16];
    __shared__ float s_bk[2];

    for (int k = tid; k < N_; k += 512) g_bwd[br*N_ + k] = 0.f;

    float accP = 0.f, accS = 0.f;
    for (int k = tid; k < N_; k += 512) {
        float t = prw[br*N_ + k];
        accP += p [b*N_ + k]*t;
        accS += ww[b*N_ + k]*t;
    }
    u64 pp = pk(accP, accS);
    #pragma unroll
    for (int m = 16; m; m >>= 1) pp = add2(pp, __shfl_xor_sync(~0u, pp, m));
    if (lane == 0) s_r1[warp] = pp;
    __syncthreads();
    if (tid == 0) {
        float P = 0.f, S = 0.f;
        #pragma unroll
        for (int i = 0; i < 16; ++i) { float x, y; upk(s_r1[i], x, y); P += x; S += y; }
        g_P[br] = P; g_S[br] = S;
        float x = controls[b*272 + 256 + r];
        s_bk[0] = 1.f + ((x > 15.f) ? x : log1pf(__expf(x)));   // beta
        float e0 = controls[b*272 + 260 + r*3 + 0];
        float e1 = controls[b*272 + 260 + r*3 + 1];
        float e2 = controls[b*272 + 260 + r*3 + 2];
        float mm = fmaxf(e0, fmaxf(e1, e2));
        float x0 = __expf(e0-mm), x1 = __expf(e1-mm), x2 = __expf(e2-mm);
        float inv = 1.f/(x0+x1+x2);
        g_gate[br*3+0] = x0*inv; g_gate[br*3+1] = x1*inv; g_gate[br*3+2] = x2*inv;
    }
    if (tid < 64) out[br*64 + tid] = 0.f;
    __syncthreads();

    float beta = s_bk[0];
    float v[4]; float mx = -1e30f;
    #pragma unroll
    for (int k = 0; k < 4; ++k) { v[k] = g_cw[br*N_ + tid + k*512]*beta; mx = fmaxf(mx, v[k]); }
    #pragma unroll
    for (int m = 16; m; m >>= 1) mx = fmaxf(mx, __shfl_xor_sync(~0u, mx, m));
    if (lane == 0) s_r2[warp] = mx;
    __syncthreads();
    if (tid == 0) { float m2 = s_r2[0]; for (int i = 1; i < 16; ++i) m2 = fmaxf(m2, s_r2[i]); s_bk[1] = m2; }
    __syncthreads();
    mx = s_bk[1];
    float s = 0.f;
    #pragma unroll
    for (int k = 0; k < 4; ++k) { v[k] = __expf(v[k]-mx); s += v[k]; }
    #pragma unroll
    for (int m = 16; m; m >>= 1) s += __shfl_xor_sync(~0u, s, m);
    __syncthreads();
    if (lane == 0) s_r2[warp] = s;
    __syncthreads();
    if (tid == 0) { float t = 0.f; for (int i = 0; i < 16; ++i) t += s_r2[i]; s_bk[0] = 1.f/t; }
    __syncthreads();
    float inv = s_bk[0];
    #pragma unroll
    for (int k = 0; k < 4; ++k) g_cw[br*N_ + tid + k*512] = v[k]*inv;
}

// ================= k_stream: one pass over L, register-prefetched LDG stream =================
// 128 blocks = 8 b x 16 tiles of 128 rows; 512 threads = 16 warps.
// Warp w owns j in [w*128, w*128+128). Lanes h=0..15 own 8 j (two float4);
// half 0/1 process even/odd row of each row-pair. No sync in the main loop.
#define SP(sel,row,w) s_part[(((sel)*128 + (row))*16) + (w)]

__global__ void __launch_bounds__(512, 1)
k_stream(const float* __restrict__ L, const float* __restrict__ ww,
         const float* __restrict__ prw, const float* __restrict__ p)
{
    __shared__ u64   s_part[2*128*16];     // 32 KB fwd partials
    __shared__ float s_a[TI_];
    __shared__ float s_pi[R_*TI_];
    __shared__ float s_diag[TI_];

    int b = blockIdx.x >> 4, tile = blockIdx.x & 15, i0 = tile*TI_;
    int tid = threadIdx.x, w = tid >> 5, lane = tid & 31;
    int half = lane >> 4, h = lane & 15;

    if (tid < TI_) {
        s_a[tid]    = 1.f - ww[b*N_ + i0 + tid];
        s_diag[tid] = __ldg(L + ((size_t)(b*N_ + i0 + tid))*N_ + i0 + tid);
    }
    if (tid < R_*TI_) s_pi[tid] = prw[(b*4 + (tid >> 7))*N_ + i0 + (tid & 127)];
    __syncthreads();

    int jA = w*128 + h*4, jB = jA + 64;
    u64 pj[4][4];
    #pragma unroll
    for (int r = 0; r < 4; ++r) {
        float4 A  = *(const float4*)(prw + (b*4+r)*N_ + jA);
        float4 Bv = *(const float4*)(prw + (b*4+r)*N_ + jB);
        pj[r][0] = pk(A.x, A.y);  pj[r][1] = pk(A.z, A.w);
        pj[r][2] = pk(Bv.x, Bv.y); pj[r][3] = pk(Bv.z, Bv.w);
    }
    float4 wA = *(const float4*)(ww + b*N_ + jA);
    float4 wB = *(const float4*)(ww + b*N_ + jB);
    u64 wj[4] = { pk(wA.x,wA.y), pk(wA.z,wA.w), pk(wB.x,wB.y), pk(wB.z,wB.w) };

    u64 bw[4][4];
    #pragma unroll
    for (int r = 0; r < 4; ++r)
        #pragma unroll
        for (int k = 0; k < 4; ++k) bw[r][k] = 0ull;

    // base pointer for this thread's (row-pair, jA) stream
    const float* Lp = L + ((size_t)(b*N_ + i0 + half))*N_ + jA;

    float4 bA0 = __ldcs((const float4*)(Lp));
    float4 bB0 = __ldcs((const float4*)(Lp + 64));
    float4 bA1 = __ldcs((const float4*)(Lp + 2*(size_t)N_));
    float4 bB1 = __ldcs((const float4*)(Lp + 2*(size_t)N_ + 64));
    float4 bA2 = __ldcs((const float4*)(Lp + 4*(size_t)N_));
    float4 bB2 = __ldcs((const float4*)(Lp + 4*(size_t)N_ + 64));

    int g = 0;

#define STEP(BA,BB) do {                                                     \
    int row = 2*g + half;                                                    \
    float4 A = BA, Bv = BB;                                                  \
    int gp = g + 3; if (gp > 63) gp = 63;                                    \
    const float* np = Lp + (size_t)(2*gp)*N_;                                \
    BA = __ldcs((const float4*)np);                                          \
    BB = __ldcs((const float4*)(np + 64));                                   \
    u64 l0 = pk(A.x,A.y), l1 = pk(A.z,A.w), l2 = pk(Bv.x,Bv.y), l3 = pk(Bv.z,Bv.w); \
    float a = s_a[row];                                                      \
    u64 av = pk(a, a);                                                       \
    u64 c0 = mul2(sub2(av, wj[0]), l0);                                      \
    u64 c1 = mul2(sub2(av, wj[1]), l1);                                      \
    u64 c2 = mul2(sub2(av, wj[2]), l2);                                      \
    u64 c3 = mul2(sub2(av, wj[3]), l3);                                      \
    float f[4];                                                              \
    _Pragma("unroll")                                                        \
    for (int r = 0; r < 4; ++r) {                                            \
        u64 t = mul2(c0, pj[r][0]);                                          \
        t = fma2(c1, pj[r][1], t);                                           \
        t = fma2(c2, pj[r][2], t);                                           \
        t = fma2(c3, pj[r][3], t);                                           \
        float x, y; upk(t, x, y); f[r] = x + y;                              \
        float pi = s_pi[r*128 + row];                                        \
        u64 pr = pk(pi, pi);                                                 \
        bw[r][0] = fma2(c0, pr, bw[r][0]);                                   \
        bw[r][1] = fma2(c1, pr, bw[r][1]);                                   \
        bw[r][2] = fma2(c2, pr, bw[r][2]);                                   \
        bw[r][3] = fma2(c3, pr, bw[r][3]);                                   \
    }                                                                        \
    u64 f01 = pk(f[0], f[1]), f23 = pk(f[2], f[3]);                          \
    _Pragma("unroll")                                                        \
    for (int m = 8; m; m >>= 1) {                                            \
        f01 = add2(f01, __shfl_xor_sync(~0u, f01, m));                       \
        f23 = add2(f23, __shfl_xor_sync(~0u, f23, m));                       \
    }                                                                        \
    if (h == 0) { SP(0, row, w) = f01; SP(1, row, w) = f23; }                \
    ++g;                                                                     \
} while (0)

    #pragma unroll 1
    for (int gb = 0; gb < 21; ++gb) {   // 63 row-pairs
        STEP(bA0, bB0);
        STEP(bA1, bB1);
        STEP(bA2, bB2);
    }
    STEP(bA0, bB0);                     // g = 63 (prefetch clamps, redundant)
#undef STEP

    // bwd: combine halves, REDG-accumulate into g_bwd
    #pragma unroll
    for (int r = 0; r < 4; ++r)
        #pragma unroll
        for (int k = 0; k < 4; ++k)
            bw[r][k] = add2(bw[r][k], __shfl_xor_sync(~0u, bw[r][k], 16));
    if (half == 0) {
        #pragma unroll
        for (int r = 0; r < 4; ++r) {
            float* dst = g_bwd + (size_t)(b*4 + r)*N_;
            float x0, x1, x2, x3, x4, x5, x6, x7;
            upk(bw[r][0], x0, x1); upk(bw[r][1], x2, x3);
            upk(bw[r][2], x4, x5); upk(bw[r][3], x6, x7);
            atomicAdd(dst + jA + 0, x0); atomicAdd(dst + jA + 1, x1);
            atomicAdd(dst + jA + 2, x2); atomicAdd(dst + jA + 3, x3);
            atomicAdd(dst + jB + 0, x4); atomicAdd(dst + jB + 1, x5);
            atomicAdd(dst + jB + 2, x6); atomicAdd(dst + jB + 3, x7);
        }
    }
    __syncthreads();

    // fwd fold + rank-1 + diag corrections; emit bwd correction g_bc
    {
        int row = tid >> 2, r = tid & 3;
        int br = b*4 + r;
        int n = i0 + row;
        const float* sp = (const float*)&SP(r >> 1, row, 0);
        float sfold = 0.f;
        #pragma unroll
        for (int w2 = 0; w2 < 16; ++w2) sfold += sp[w2*2 + (r & 1)];
        float wn  = 1.f - s_a[row];
        float pn  = p[b*N_ + n];
        float prn = s_pi[r*128 + row];
        float ell = (1.f - 2.f*wn)*s_diag[row] + wn*pn;
        g_fwd[br*N_ + n] = sfold + wn*g_P[br] - ell*prn;
        g_bc [br*N_ + n] = pn*g_S[br] - ell*prn;
    }
}

// ================= k_post: rw assembly + read vector, 256 blocks x 256 =================
__global__ void __launch_bounds__(256, 1)
k_post(const float* __restrict__ mem, float* __restrict__ out)
{
    int b = blockIdx.x >> 5, c = blockIdx.x & 31;
    int n0 = c*64;
    int tid = threadIdx.x, warp = tid >> 5, lane = tid & 31;
    __shared__ float s_rw[4][64];
    __shared__ float s_g[12];
    __shared__ float s_acc[8][4][64];

    if (tid < 12) s_g[tid] = g_gate[b*12 + tid];
    __syncthreads();

    {
        int r = tid >> 6, nl = tid & 63;
        int br = b*4 + r, n = n0 + nl;
        s_rw[r][nl] = s_g[r*3+0]*g_fwd[br*N_ + n]
                    + s_g[r*3+1]*(g_bwd[br*N_ + n] + g_bc[br*N_ + n])
                    + s_g[r*3+2]*g_cw[br*N_ + n];
    }
    __syncthreads();

    float2 acc[4];
    #pragma unroll
    for (int r = 0; r < 4; ++r) { acc[r].x = 0.f; acc[r].y = 0.f; }
    #pragma unroll
    for (int k = 0; k < 8; ++k) {
        int nl = warp*8 + k;
        float2 m = *(const float2*)(mem + ((size_t)(b*N_ + n0 + nl))*W_ + lane*2);
        #pragma unroll
        for (int r = 0; r < 4; ++r) {
            float rv = s_rw[r][nl];
            acc[r].x += m.x*rv;
            acc[r].y += m.y*rv;
        }
    }
    #pragma unroll
    for (int r = 0; r < 4; ++r) {
        s_acc[warp][r][lane*2]   = acc[r].x;
        s_acc[warp][r][lane*2+1] = acc[r].y;
    }
    __syncthreads();
    {
        int r = tid >> 6, wd = tid & 63;
        float s = 0.f;
        #pragma unroll
        for (int k = 0; k < 8; ++k) s += s_acc[k][r][wd];
        atomicAdd(&out[(b*4 + r)*64 + wd], s);
    }
}

// ================= launcher =================
extern "C" void kernel_launch(void* const* d_in, const int* in_sizes, int n_in,
                              void* d_out, int out_size)
{
    const float* mem      = (const float*)d_in[0];
    const float* controls = (const float*)d_in[1];
    const float* ww       = (const float*)d_in[2];
    const float* L        = (const float*)d_in[3];
    const float* p        = (const float*)d_in[4];
    const float* prw      = (const float*)d_in[5];
    float* out = (float*)d_out;

    k_dots  <<<B_*16, 512>>>(mem, controls);
    k_smax  <<<B_*R_, 512>>>(controls, ww, p, prw, out);
    k_stream<<<B_*16, 512>>>(L, ww, prw, p);
    k_post  <<<B_*32, 256>>>(mem, out);
}